// round 1
// baseline (speedup 1.0000x reference)
#include <cuda_runtime.h>

// DynamicLinearModel: out[r,t] = theta[r,t] + X[t]·eta[r] + Z[t]·zeta[r]
//   theta_t = a_r * theta_{t-1} + b_{t-1},  b_t = Z[t]·gamma[r],  a_r = sigmoid(G[r])
// R=4096, T=2048, XD=ZD=8.
//
// Strategy: fma-pipe-bound problem. Pack all dot products across the k-dim with
// fma.rn.f32x2 (pairs come directly from LDG.128 register pairs). The sequential
// scan over t is parallelized by splitting each row into 32 chunks of 64:
//   Pass A: per-chunk decay-weighted sum W_c (recompute b, cheap)
//   Scan:   warp-shuffle weighted scan with multiplier a^64 -> chunk carries
//   Pass B: replay recurrence from carry, fuse dot products, float4 stores.

#define R_DIM 4096
#define T_DIM 2048
#define XD 8
#define ZD 8
#define RPB 8                    // rows per block
#define CH 32                    // chunks per row
#define LCH (T_DIM / CH)         // 64 timesteps per chunk
#define NTHREADS (RPB * CH)      // 256

__device__ __forceinline__ unsigned long long ffma2(unsigned long long x,
                                                    unsigned long long w,
                                                    unsigned long long c) {
    unsigned long long d;
    asm("fma.rn.f32x2 %0, %1, %2, %3;" : "=l"(d) : "l"(x), "l"(w), "l"(c));
    return d;
}
__device__ __forceinline__ unsigned long long pack2(float lo, float hi) {
    unsigned long long d;
    asm("mov.b64 %0, {%1, %2};" : "=l"(d) : "f"(lo), "f"(hi));
    return d;
}
__device__ __forceinline__ float hsum2(unsigned long long v) {
    float lo, hi;
    asm("mov.b64 {%0, %1}, %2;" : "=f"(lo), "=f"(hi) : "l"(v));
    return lo + hi;
}

union F4U { float4 f; unsigned long long u[2]; };

__global__ void __launch_bounds__(NTHREADS)
dlm_kernel(const float* __restrict__ X, const float* __restrict__ Z,
           const float* __restrict__ G, const float* __restrict__ eta,
           const float* __restrict__ zeta, const float* __restrict__ gamma,
           float* __restrict__ out)
{
    __shared__ float Wbuf[RPB][CH + 1];   // chunk summaries (padded vs conflicts)
    __shared__ float Cbuf[RPB][CH + 1];   // chunk carries

    const int tid = threadIdx.x;
    const int rl  = tid & (RPB - 1);      // row within block
    const int c   = tid >> 3;             // chunk id 0..31
    const int r   = blockIdx.x * RPB + rl;

    const float a = 1.0f / (1.0f + expf(-G[r]));

    // Per-row weights, packed as f32x2 pairs straight from float4 loads.
    F4U g0, g1, e0, e1, s0, s1;
    g0.f = *(const float4*)(gamma + r * ZD);
    g1.f = *(const float4*)(gamma + r * ZD + 4);
    e0.f = *(const float4*)(eta   + r * XD);
    e1.f = *(const float4*)(eta   + r * XD + 4);
    s0.f = *(const float4*)(zeta  + r * ZD);
    s1.f = *(const float4*)(zeta  + r * ZD + 4);

    const float* zp = Z + (size_t)c * LCH * ZD;
    const float* xp = X + (size_t)c * LCH * XD;

    // ---- Pass A: W_c = sum_{i<L} a^{L-1-i} * b_{cL+i} ----
    float V = 0.0f;
    #pragma unroll 4
    for (int i = 0; i < LCH; i++) {
        F4U z0, z1;
        z0.f = *(const float4*)(zp + i * ZD);
        z1.f = *(const float4*)(zp + i * ZD + 4);
        unsigned long long bb = ffma2(z0.u[0], g0.u[0], pack2(0.0f, 0.0f));
        bb = ffma2(z0.u[1], g0.u[1], bb);
        bb = ffma2(z1.u[0], g1.u[0], bb);
        bb = ffma2(z1.u[1], g1.u[1], bb);
        V = fmaf(a, V, hsum2(bb));
    }
    Wbuf[rl][c] = V;
    __syncthreads();

    // ---- Weighted exclusive scan over chunks (warp w handles row w) ----
    {
        const int w    = tid >> 5;        // 8 warps == RPB rows
        const int lane = tid & 31;
        const float aw = 1.0f / (1.0f + expf(-G[blockIdx.x * RPB + w]));
        float q = aw;
        #pragma unroll
        for (int k = 0; k < 6; k++) q *= q;   // aw^64
        float s = Wbuf[w][lane];
        float m = q;
        #pragma unroll
        for (int d = 1; d < 32; d <<= 1) {
            float up = __shfl_up_sync(0xffffffffu, s, d);
            if (lane >= d) s = fmaf(m, up, s);
            m *= m;
        }
        // carry_c = inclusive[c-1]; carry_0 = 0
        if (lane == 0)  Cbuf[w][0] = 0.0f;
        if (lane < 31)  Cbuf[w][lane + 1] = s;
    }
    __syncthreads();

    // ---- Pass B: replay recurrence from carry, fused dots, vector stores ----
    float theta = Cbuf[rl][c];
    float* op = out + (size_t)r * T_DIM + (size_t)c * LCH;

    #pragma unroll 2
    for (int i = 0; i < LCH; i += 4) {
        float res[4];
        #pragma unroll
        for (int j = 0; j < 4; j++) {
            F4U x0, x1, z0, z1;
            x0.f = *(const float4*)(xp + (i + j) * XD);
            x1.f = *(const float4*)(xp + (i + j) * XD + 4);
            z0.f = *(const float4*)(zp + (i + j) * ZD);
            z1.f = *(const float4*)(zp + (i + j) * ZD + 4);

            // xz accumulator seeded with {theta, 0}: out = lo+hi at the end
            unsigned long long xz = pack2(theta, 0.0f);
            xz = ffma2(x0.u[0], e0.u[0], xz);
            xz = ffma2(x0.u[1], e0.u[1], xz);
            xz = ffma2(x1.u[0], e1.u[0], xz);
            xz = ffma2(x1.u[1], e1.u[1], xz);
            xz = ffma2(z0.u[0], s0.u[0], xz);
            xz = ffma2(z0.u[1], s0.u[1], xz);
            xz = ffma2(z1.u[0], s1.u[0], xz);
            xz = ffma2(z1.u[1], s1.u[1], xz);

            unsigned long long bb = ffma2(z0.u[0], g0.u[0], pack2(0.0f, 0.0f));
            bb = ffma2(z0.u[1], g0.u[1], bb);
            bb = ffma2(z1.u[0], g1.u[0], bb);
            bb = ffma2(z1.u[1], g1.u[1], bb);

            res[j] = hsum2(xz);                       // theta_t + x_term + z_term
            theta  = fmaf(a, theta, hsum2(bb));       // theta_{t+1} = a*theta_t + b_t
        }
        float4 ov;
        ov.x = res[0]; ov.y = res[1]; ov.z = res[2]; ov.w = res[3];
        *(float4*)(op + i) = ov;
    }
}

extern "C" void kernel_launch(void* const* d_in, const int* in_sizes, int n_in,
                              void* d_out, int out_size) {
    const float* X     = (const float*)d_in[0];
    const float* Z     = (const float*)d_in[1];
    const float* G     = (const float*)d_in[2];
    const float* eta   = (const float*)d_in[3];
    const float* zeta  = (const float*)d_in[4];
    const float* gamma = (const float*)d_in[5];
    float* out = (float*)d_out;
    dlm_kernel<<<R_DIM / RPB, NTHREADS>>>(X, Z, G, eta, zeta, gamma, out);
}

// round 3
// speedup vs baseline: 1.4342x; 1.4342x over previous
#include <cuda_runtime.h>

// DynamicLinearModel: out[r,t] = theta[r,t] + X[t]·eta[r] + Z[t]·zeta[r]
//   theta_t = a_r*theta_{t-1} + b_{t-1},  b_t = Z[t]·gamma[r],  a_r = sigmoid(G[r])
// R=4096, T=2048, XD=ZD=8.
//
// R1 design (resubmitted after infra flake): L1-wavefront-bound fix.
//  - 4 rows/thread: X/Z traffic amortized 4x; weights in f32x2 register pairs.
//  - X/Z slab staged in padded SMEM (conflict-free LDS.128 vs 8-wavefront LDG).
//  - Block = 32 rows x full T; grid = 128 = one wave on 148 SMs.
//  - Chunked decay scan: 64 chunks of 32; pair-combine warp shuffle scan.

#define T_DIM 2048
#define R_DIM 4096
#define XD 8
#define ZD 8
#define RB 32                    // rows per block
#define CH 64                    // chunks per row
#define LCH (T_DIM / CH)         // 32 timesteps per chunk
#define RPT 4                    // rows per thread
#define GROUPS (RB / RPT)        // 8
#define NT (CH * GROUPS)         // 512 threads

// Padded slab layout: per timestep 8 floats; +4 floats pad per 32-t chunk so
// the 4 chunk-groups in a warp hit disjoint 16B bank quads.
#define SLAB_F (T_DIM * 8 + CH * 4)   // 16640 floats
#define WSTRIDE 68                     // Wb/Cb row stride (pad vs bank conflicts)
#define SMEM_F (2 * SLAB_F + 2 * RB * WSTRIDE)
#define SMEM_BYTES (SMEM_F * 4)

__device__ __forceinline__ unsigned long long ffma2(unsigned long long x,
                                                    unsigned long long w,
                                                    unsigned long long c) {
    unsigned long long d;
    asm("fma.rn.f32x2 %0, %1, %2, %3;" : "=l"(d) : "l"(x), "l"(w), "l"(c));
    return d;
}
__device__ __forceinline__ unsigned long long pack2(float lo, float hi) {
    unsigned long long d;
    asm("mov.b64 %0, {%1, %2};" : "=l"(d) : "f"(lo), "f"(hi));
    return d;
}
__device__ __forceinline__ float hsum2(unsigned long long v) {
    float lo, hi;
    asm("mov.b64 {%0, %1}, %2;" : "=f"(lo), "=f"(hi) : "l"(v));
    return lo + hi;
}
__device__ __forceinline__ float sigmoidf_(float x) {
    return 1.0f / (1.0f + expf(-x));
}

union F4U { float4 f; unsigned long long u[2]; };

__global__ void __launch_bounds__(NT, 1)
dlm_kernel(const float* __restrict__ X, const float* __restrict__ Z,
           const float* __restrict__ G, const float* __restrict__ eta,
           const float* __restrict__ zeta, const float* __restrict__ gamma,
           float* __restrict__ out)
{
    extern __shared__ float sm[];
    float* Xs = sm;
    float* Zs = sm + SLAB_F;
    float* Wb = sm + 2 * SLAB_F;
    float* Cb = Wb + RB * WSTRIDE;

    const int tid = threadIdx.x;
    const int g   = tid & (GROUPS - 1);   // row-quad 0..7
    const int c   = tid >> 3;             // chunk 0..63
    const int r0  = blockIdx.x * RB + g * RPT;

    // ---- cooperative slab load (coalesced float4) ----
    for (int v = tid; v < T_DIM * 2; v += NT) {
        int t = v >> 1, h = v & 1;
        int off = t * 8 + (t >> 5) * 4 + h * 4;   // padded offset (floats)
        *(float4*)(Xs + off) = ((const float4*)X)[v];
        *(float4*)(Zs + off) = ((const float4*)Z)[v];
    }

    // ---- per-row weights as f32x2 pairs ----
    F4U e0[RPT], e1[RPT], s0[RPT], s1[RPT], g0[RPT], g1[RPT];
    float a[RPT];
    #pragma unroll
    for (int j = 0; j < RPT; j++) {
        int r = r0 + j;
        a[j]  = sigmoidf_(G[r]);
        e0[j].f = *(const float4*)(eta   + r * XD);
        e1[j].f = *(const float4*)(eta   + r * XD + 4);
        s0[j].f = *(const float4*)(zeta  + r * ZD);
        s1[j].f = *(const float4*)(zeta  + r * ZD + 4);
        g0[j].f = *(const float4*)(gamma + r * ZD);
        g1[j].f = *(const float4*)(gamma + r * ZD + 4);
    }
    __syncthreads();

    const float* zp = Zs + c * (LCH * 8 + 4);   // 260 floats per chunk
    const float* xp = Xs + c * (LCH * 8 + 4);

    // ---- Pass A: per-chunk decay-weighted sums W_c for 4 rows ----
    float V[RPT] = {0.f, 0.f, 0.f, 0.f};
    #pragma unroll 4
    for (int i = 0; i < LCH; i++) {
        F4U z0, z1;
        z0.f = *(const float4*)(zp + i * 8);
        z1.f = *(const float4*)(zp + i * 8 + 4);
        #pragma unroll
        for (int j = 0; j < RPT; j++) {
            unsigned long long bb = ffma2(z0.u[0], g0[j].u[0], pack2(0.f, 0.f));
            bb = ffma2(z0.u[1], g0[j].u[1], bb);
            bb = ffma2(z1.u[0], g1[j].u[0], bb);
            bb = ffma2(z1.u[1], g1[j].u[1], bb);
            V[j] = fmaf(a[j], V[j], hsum2(bb));
        }
    }
    #pragma unroll
    for (int j = 0; j < RPT; j++)
        Wb[(g * RPT + j) * WSTRIDE + c] = V[j];
    __syncthreads();

    // ---- weighted exclusive scan over 64 chunks (pair trick, 2 rows/warp) ----
    {
        const int w    = tid >> 5;     // 16 warps -> rows 2w, 2w+1
        const int lane = tid & 31;
        #pragma unroll
        for (int rr = 0; rr < 2; rr++) {
            int row = w * 2 + rr;
            float ar = sigmoidf_(G[blockIdx.x * RB + row]);
            float q = ar;
            #pragma unroll
            for (int k = 0; k < 5; k++) q *= q;          // ar^32 = ar^LCH
            float2 uv = *(const float2*)(Wb + row * WSTRIDE + 2 * lane);
            float pA = fmaf(q, uv.x, uv.y);              // combined pair value
            float m = q * q;                             // pair multiplier
            float s = pA;
            #pragma unroll
            for (int d = 1; d < 32; d <<= 1) {
                float up = __shfl_up_sync(0xffffffffu, s, d);
                if (lane >= d) s = fmaf(m, up, s);
                m *= m;
            }
            float e = __shfl_up_sync(0xffffffffu, s, 1); // exclusive pair carry
            if (lane == 0) e = 0.0f;
            Cb[row * WSTRIDE + 2 * lane]     = e;
            Cb[row * WSTRIDE + 2 * lane + 1] = fmaf(q, e, uv.x);
        }
    }
    __syncthreads();

    // ---- Pass B: replay recurrence, fused dots, float4 stores ----
    float th[RPT];
    #pragma unroll
    for (int j = 0; j < RPT; j++)
        th[j] = Cb[(g * RPT + j) * WSTRIDE + c];

    float* op = out + (size_t)r0 * T_DIM + c * LCH;

    for (int i = 0; i < LCH; i += 4) {
        float res[RPT][4];
        #pragma unroll
        for (int tt = 0; tt < 4; tt++) {
            F4U x0, x1, z0, z1;
            x0.f = *(const float4*)(xp + (i + tt) * 8);
            x1.f = *(const float4*)(xp + (i + tt) * 8 + 4);
            z0.f = *(const float4*)(zp + (i + tt) * 8);
            z1.f = *(const float4*)(zp + (i + tt) * 8 + 4);
            #pragma unroll
            for (int j = 0; j < RPT; j++) {
                unsigned long long xz = pack2(th[j], 0.0f);
                xz = ffma2(x0.u[0], e0[j].u[0], xz);
                xz = ffma2(x0.u[1], e0[j].u[1], xz);
                xz = ffma2(x1.u[0], e1[j].u[0], xz);
                xz = ffma2(x1.u[1], e1[j].u[1], xz);
                xz = ffma2(z0.u[0], s0[j].u[0], xz);
                xz = ffma2(z0.u[1], s0[j].u[1], xz);
                xz = ffma2(z1.u[0], s1[j].u[0], xz);
                xz = ffma2(z1.u[1], s1[j].u[1], xz);

                unsigned long long bb = ffma2(z0.u[0], g0[j].u[0], pack2(0.f, 0.f));
                bb = ffma2(z0.u[1], g0[j].u[1], bb);
                bb = ffma2(z1.u[0], g1[j].u[0], bb);
                bb = ffma2(z1.u[1], g1[j].u[1], bb);

                res[j][tt] = hsum2(xz);
                th[j] = fmaf(a[j], th[j], hsum2(bb));
            }
        }
        #pragma unroll
        for (int j = 0; j < RPT; j++) {
            float4 ov;
            ov.x = res[j][0]; ov.y = res[j][1]; ov.z = res[j][2]; ov.w = res[j][3];
            *(float4*)(op + (size_t)j * T_DIM + i) = ov;
        }
    }
}

extern "C" void kernel_launch(void* const* d_in, const int* in_sizes, int n_in,
                              void* d_out, int out_size) {
    const float* X     = (const float*)d_in[0];
    const float* Z     = (const float*)d_in[1];
    const float* G     = (const float*)d_in[2];
    const float* eta   = (const float*)d_in[3];
    const float* zeta  = (const float*)d_in[4];
    const float* gamma = (const float*)d_in[5];
    float* out = (float*)d_out;

    cudaFuncSetAttribute(dlm_kernel,
                         cudaFuncAttributeMaxDynamicSharedMemorySize, SMEM_BYTES);
    dlm_kernel<<<R_DIM / RB, NT, SMEM_BYTES>>>(X, Z, G, eta, zeta, gamma, out);
}

// round 4
// speedup vs baseline: 2.9050x; 2.0255x over previous
#include <cuda_runtime.h>

// DynamicLinearModel: out[r,t] = theta[r,t] + X[t]·eta[r] + Z[t]·zeta[r]
//   theta_{t+1} = a_r*theta_t + b_t,  b_t = Z[t]·gamma[r],  a_r = sigmoid(G[r]), theta_0=0
// R=4096, T=2048, XD=ZD=8.
//
// R3 design: serial-T warp sweep, fully coalesced I/O.
//  - warp owns 4 rows x full T; 16 chunks of 128 t; carry in register.
//  - lane l owns t=4l..4l+3 of each chunk: warp-scan (mult a^4) for theta starts,
//    4-step replay, float4 stores with lanes contiguous (4 full lines / STG.128).
//  - X/Z in 128KB XOR-swizzled SMEM slab: conflict-free lane-contiguous LDS.128.
//  - grid 148 x 7 warps = 1036 warps covering 1024 row-quads.

#define T_DIM 2048
#define R_DIM 4096
#define NWARP 7
#define NT (NWARP * 32)
#define NQUAD (R_DIM / 4)     // 1024
#define GRID 148
#define SLAB_BYTES 65536      // per slab (t * 32B)
#define SMEM_BYTES (2 * SLAB_BYTES)

__device__ __forceinline__ unsigned long long ffma2(unsigned long long x,
                                                    unsigned long long w,
                                                    unsigned long long c) {
    unsigned long long d;
    asm("fma.rn.f32x2 %0, %1, %2, %3;" : "=l"(d) : "l"(x), "l"(w), "l"(c));
    return d;
}
__device__ __forceinline__ unsigned long long pack2(float lo, float hi) {
    unsigned long long d;
    asm("mov.b64 %0, {%1, %2};" : "=l"(d) : "f"(lo), "f"(hi));
    return d;
}
__device__ __forceinline__ float hsum2(unsigned long long v) {
    float lo, hi;
    asm("mov.b64 {%0, %1}, %2;" : "=f"(lo), "=f"(hi) : "l"(v));
    return lo + hi;
}
// XOR-128 swizzle on byte offsets: spreads 128B-strided lanes across 16B quads.
__device__ __forceinline__ int swz(int ob) {
    return ob ^ (((ob >> 7) & 7) << 4);
}

union F4U { float4 f; unsigned long long u[2]; };

__global__ void __launch_bounds__(NT, 1)
dlm_kernel(const float* __restrict__ X, const float* __restrict__ Z,
           const float* __restrict__ G, const float* __restrict__ eta,
           const float* __restrict__ zeta, const float* __restrict__ gamma,
           float* __restrict__ out)
{
    extern __shared__ char sm[];
    char* Xs = sm;
    char* Zs = sm + SLAB_BYTES;

    const int tid  = threadIdx.x;
    const int w    = tid >> 5;
    const int lane = tid & 31;

    // ---- cooperative swizzled slab load (all threads) ----
    for (int v = tid; v < T_DIM * 2; v += NT) {
        int ob = v * 16;                       // t*32 + h*16
        int po = swz(ob);
        *(float4*)(Xs + po) = ((const float4*)X)[v];
        *(float4*)(Zs + po) = ((const float4*)Z)[v];
    }
    __syncthreads();

    const int quad = w * GRID + blockIdx.x;
    if (quad >= NQUAD) return;
    const int r0 = quad * 4;

    // ---- per-row constants ----
    F4U e0[4], e1[4], s0[4], s1[4], g0[4], g1[4];
    float a[4], m0[4], m1[4], m2[4], m3[4], m4[4], a128[4], pa4l[4], C[4];
    #pragma unroll
    for (int j = 0; j < 4; j++) {
        int r = r0 + j;
        a[j] = 1.0f / (1.0f + expf(-G[r]));
        e0[j].f = *(const float4*)(eta   + r * 8);
        e1[j].f = *(const float4*)(eta   + r * 8 + 4);
        s0[j].f = *(const float4*)(zeta  + r * 8);
        s1[j].f = *(const float4*)(zeta  + r * 8 + 4);
        g0[j].f = *(const float4*)(gamma + r * 8);
        g1[j].f = *(const float4*)(gamma + r * 8 + 4);
        float a2 = a[j] * a[j];
        float a4 = a2 * a2;
        m0[j] = a4;                 // scan multipliers a^4 * 2^k
        m1[j] = m0[j] * m0[j];
        m2[j] = m1[j] * m1[j];
        m3[j] = m2[j] * m2[j];
        m4[j] = m3[j] * m3[j];
        a128[j] = m4[j] * m4[j];    // a^128 (chunk carry multiplier)
        // pa4l = a^(4*lane) by repeated squaring over lane bits
        float p = a4, v = 1.0f;
        #pragma unroll
        for (int k = 0; k < 5; k++) {
            if (lane & (1 << k)) v *= p;
            p *= p;
        }
        pa4l[j] = v;
        C[j] = 0.0f;                // theta_0 = 0
    }

    float* outp = out + (size_t)r0 * T_DIM + 4 * lane;

    // ---- serial sweep over 16 chunks of 128 t ----
    for (int tb = 0; tb < T_DIM; tb += 128) {
        // load x/z for lane's 4 timesteps (conflict-free swizzled LDS.128)
        F4U xv[4][2], zv[4][2];
        #pragma unroll
        for (int k = 0; k < 4; k++) {
            int ob = (tb + 4 * lane + k) * 32;
            xv[k][0].f = *(const float4*)(Xs + swz(ob));
            xv[k][1].f = *(const float4*)(Xs + swz(ob + 16));
            zv[k][0].f = *(const float4*)(Zs + swz(ob));
            zv[k][1].f = *(const float4*)(Zs + swz(ob + 16));
        }

        float res[4][4];
        #pragma unroll
        for (int j = 0; j < 4; j++) {
            // b_k = Z[t]·gamma_j for lane's 4 t
            float b[4];
            #pragma unroll
            for (int k = 0; k < 4; k++) {
                unsigned long long bb = ffma2(zv[k][0].u[0], g0[j].u[0], pack2(0.f, 0.f));
                bb = ffma2(zv[k][0].u[1], g0[j].u[1], bb);
                bb = ffma2(zv[k][1].u[0], g1[j].u[0], bb);
                bb = ffma2(zv[k][1].u[1], g1[j].u[1], bb);
                b[k] = hsum2(bb);
            }
            // local combine: w = a^3 b0 + a^2 b1 + a b2 + b3
            float wv = fmaf(fmaf(fmaf(b[0], a[j], b[1]), a[j], b[2]), a[j], b[3]);
            // inclusive weighted warp scan, multiplier a^4
            float s = wv;
            float up;
            up = __shfl_up_sync(0xffffffffu, s, 1);  if (lane >= 1)  s = fmaf(m0[j], up, s);
            up = __shfl_up_sync(0xffffffffu, s, 2);  if (lane >= 2)  s = fmaf(m1[j], up, s);
            up = __shfl_up_sync(0xffffffffu, s, 4);  if (lane >= 4)  s = fmaf(m2[j], up, s);
            up = __shfl_up_sync(0xffffffffu, s, 8);  if (lane >= 8)  s = fmaf(m3[j], up, s);
            up = __shfl_up_sync(0xffffffffu, s, 16); if (lane >= 16) s = fmaf(m4[j], up, s);
            float E = __shfl_up_sync(0xffffffffu, s, 1);
            if (lane == 0) E = 0.0f;
            float W = __shfl_sync(0xffffffffu, s, 31);
            // theta at lane start; update carry for next chunk
            float th = fmaf(pa4l[j], C[j], E);
            C[j] = fmaf(a128[j], C[j], W);
            // replay 4 steps, fusing the x/z dot
            #pragma unroll
            for (int k = 0; k < 4; k++) {
                unsigned long long xz = pack2(th, 0.0f);
                xz = ffma2(xv[k][0].u[0], e0[j].u[0], xz);
                xz = ffma2(xv[k][0].u[1], e0[j].u[1], xz);
                xz = ffma2(xv[k][1].u[0], e1[j].u[0], xz);
                xz = ffma2(xv[k][1].u[1], e1[j].u[1], xz);
                xz = ffma2(zv[k][0].u[0], s0[j].u[0], xz);
                xz = ffma2(zv[k][0].u[1], s0[j].u[1], xz);
                xz = ffma2(zv[k][1].u[0], s1[j].u[0], xz);
                xz = ffma2(zv[k][1].u[1], s1[j].u[1], xz);
                res[j][k] = hsum2(xz);
                th = fmaf(a[j], th, b[k]);
            }
        }
        // coalesced stores: lanes contiguous in t (4 full 128B lines / STG.128)
        #pragma unroll
        for (int j = 0; j < 4; j++) {
            float4 ov;
            ov.x = res[j][0]; ov.y = res[j][1]; ov.z = res[j][2]; ov.w = res[j][3];
            *(float4*)(outp + (size_t)j * T_DIM + tb) = ov;
        }
    }
}

extern "C" void kernel_launch(void* const* d_in, const int* in_sizes, int n_in,
                              void* d_out, int out_size) {
    const float* X     = (const float*)d_in[0];
    const float* Z     = (const float*)d_in[1];
    const float* G     = (const float*)d_in[2];
    const float* eta   = (const float*)d_in[3];
    const float* zeta  = (const float*)d_in[4];
    const float* gamma = (const float*)d_in[5];
    float* out = (float*)d_out;

    cudaFuncSetAttribute(dlm_kernel,
                         cudaFuncAttributeMaxDynamicSharedMemorySize, SMEM_BYTES);
    dlm_kernel<<<GRID, NT, SMEM_BYTES>>>(X, Z, G, eta, zeta, gamma, out);
}

// round 6
// speedup vs baseline: 2.9767x; 1.0247x over previous
#include <cuda_runtime.h>

// DynamicLinearModel: out[r,t] = theta[r,t] + X[t]·eta[r] + Z[t]·zeta[r]
//   theta_{t+1} = a_r*theta_t + b_t,  b_t = Z[t]·gamma[r],  a_r = sigmoid(G[r]), theta_0=0
// R=4096, T=2048, XD=ZD=8.
//
// R4 design (resubmitted after infra flake): latency-bound fix — 2x warps via
// RPT=2 + register diet.
//  - warp owns 2 rows x full T; 16 chunks of 128 t; carry in register.
//  - per chunk: per-k transient loads compute b[k]=Z·gamma and d[k]=X·eta+Z·zeta
//    (scalars only live across the scan), warp-scan (mult a^4) for theta starts,
//    replay is scalar fma; float4 stores with lanes contiguous in t.
//  - X/Z in 128KB XOR-swizzled SMEM slab, conflict-free LDS.128.
//  - grid 148 x 14 warps = 2072 warps covering 2048 row-pairs.

#define T_DIM 2048
#define R_DIM 4096
#define RPT 2
#define NWARP 14
#define NT (NWARP * 32)          // 448
#define NPAIR (R_DIM / RPT)      // 2048
#define GRID 148
#define SLAB_BYTES 65536
#define SMEM_BYTES (2 * SLAB_BYTES)

__device__ __forceinline__ unsigned long long ffma2(unsigned long long x,
                                                    unsigned long long w,
                                                    unsigned long long c) {
    unsigned long long d;
    asm("fma.rn.f32x2 %0, %1, %2, %3;" : "=l"(d) : "l"(x), "l"(w), "l"(c));
    return d;
}
__device__ __forceinline__ unsigned long long pack2(float lo, float hi) {
    unsigned long long d;
    asm("mov.b64 %0, {%1, %2};" : "=l"(d) : "f"(lo), "f"(hi));
    return d;
}
__device__ __forceinline__ float hsum2(unsigned long long v) {
    float lo, hi;
    asm("mov.b64 {%0, %1}, %2;" : "=f"(lo), "=f"(hi) : "l"(v));
    return lo + hi;
}
// XOR-128 swizzle on byte offsets: spreads 128B-strided lanes across 16B quads.
__device__ __forceinline__ int swz(int ob) {
    return ob ^ (((ob >> 7) & 7) << 4);
}

union F4U { float4 f; unsigned long long u[2]; };

__global__ void __launch_bounds__(NT, 1)
dlm_kernel(const float* __restrict__ X, const float* __restrict__ Z,
           const float* __restrict__ G, const float* __restrict__ eta,
           const float* __restrict__ zeta, const float* __restrict__ gamma,
           float* __restrict__ out)
{
    extern __shared__ char sm[];
    char* Xs = sm;
    char* Zs = sm + SLAB_BYTES;

    const int tid  = threadIdx.x;
    const int w    = tid >> 5;
    const int lane = tid & 31;

    // ---- cooperative swizzled slab load ----
    for (int v = tid; v < T_DIM * 2; v += NT) {
        int po = swz(v * 16);
        *(float4*)(Xs + po) = ((const float4*)X)[v];
        *(float4*)(Zs + po) = ((const float4*)Z)[v];
    }
    __syncthreads();

    const int pair = w * GRID + blockIdx.x;
    if (pair >= NPAIR) return;
    const int r0 = pair * RPT;

    // ---- per-row constants ----
    F4U e0[RPT], e1[RPT], s0[RPT], s1[RPT], g0[RPT], g1[RPT];
    float a[RPT], m0[RPT], m1[RPT], m2[RPT], m3[RPT], m4[RPT],
          a128[RPT], pa4l[RPT], C[RPT];
    #pragma unroll
    for (int j = 0; j < RPT; j++) {
        int r = r0 + j;
        a[j] = 1.0f / (1.0f + expf(-G[r]));
        e0[j].f = *(const float4*)(eta   + r * 8);
        e1[j].f = *(const float4*)(eta   + r * 8 + 4);
        s0[j].f = *(const float4*)(zeta  + r * 8);
        s1[j].f = *(const float4*)(zeta  + r * 8 + 4);
        g0[j].f = *(const float4*)(gamma + r * 8);
        g1[j].f = *(const float4*)(gamma + r * 8 + 4);
        float a2 = a[j] * a[j];
        float a4 = a2 * a2;
        m0[j] = a4;
        m1[j] = m0[j] * m0[j];
        m2[j] = m1[j] * m1[j];
        m3[j] = m2[j] * m2[j];
        m4[j] = m3[j] * m3[j];
        a128[j] = m4[j] * m4[j];
        float p = a4, v = 1.0f;
        #pragma unroll
        for (int k = 0; k < 5; k++) {
            if (lane & (1 << k)) v *= p;
            p *= p;
        }
        pa4l[j] = v;
        C[j] = 0.0f;
    }

    float* outp = out + (size_t)r0 * T_DIM + 4 * lane;

    // ---- serial sweep over 16 chunks of 128 t ----
    for (int tb = 0; tb < T_DIM; tb += 128) {
        // Phase 1: per-k transient loads -> scalars b (Z·gamma), d (X·eta+Z·zeta)
        float b[RPT][4], d[RPT][4];
        #pragma unroll
        for (int k = 0; k < 4; k++) {
            int ob = (tb + 4 * lane + k) * 32;
            F4U x0, x1, z0, z1;
            x0.f = *(const float4*)(Xs + swz(ob));
            x1.f = *(const float4*)(Xs + swz(ob + 16));
            z0.f = *(const float4*)(Zs + swz(ob));
            z1.f = *(const float4*)(Zs + swz(ob + 16));
            #pragma unroll
            for (int j = 0; j < RPT; j++) {
                unsigned long long bb = ffma2(z0.u[0], g0[j].u[0], pack2(0.f, 0.f));
                bb = ffma2(z0.u[1], g0[j].u[1], bb);
                bb = ffma2(z1.u[0], g1[j].u[0], bb);
                bb = ffma2(z1.u[1], g1[j].u[1], bb);
                b[j][k] = hsum2(bb);

                unsigned long long xz = ffma2(x0.u[0], e0[j].u[0], pack2(0.f, 0.f));
                xz = ffma2(x0.u[1], e0[j].u[1], xz);
                xz = ffma2(x1.u[0], e1[j].u[0], xz);
                xz = ffma2(x1.u[1], e1[j].u[1], xz);
                xz = ffma2(z0.u[0], s0[j].u[0], xz);
                xz = ffma2(z0.u[1], s0[j].u[1], xz);
                xz = ffma2(z1.u[0], s1[j].u[0], xz);
                xz = ffma2(z1.u[1], s1[j].u[1], xz);
                d[j][k] = hsum2(xz);
            }
        }

        // Phase 2: per-row warp scan + scalar replay + coalesced store
        #pragma unroll
        for (int j = 0; j < RPT; j++) {
            float wv = fmaf(fmaf(fmaf(b[j][0], a[j], b[j][1]), a[j], b[j][2]),
                            a[j], b[j][3]);
            float s = wv, up;
            up = __shfl_up_sync(0xffffffffu, s, 1);  if (lane >= 1)  s = fmaf(m0[j], up, s);
            up = __shfl_up_sync(0xffffffffu, s, 2);  if (lane >= 2)  s = fmaf(m1[j], up, s);
            up = __shfl_up_sync(0xffffffffu, s, 4);  if (lane >= 4)  s = fmaf(m2[j], up, s);
            up = __shfl_up_sync(0xffffffffu, s, 8);  if (lane >= 8)  s = fmaf(m3[j], up, s);
            up = __shfl_up_sync(0xffffffffu, s, 16); if (lane >= 16) s = fmaf(m4[j], up, s);
            float E = __shfl_up_sync(0xffffffffu, s, 1);
            if (lane == 0) E = 0.0f;
            float W = __shfl_sync(0xffffffffu, s, 31);

            float th = fmaf(pa4l[j], C[j], E);
            C[j] = fmaf(a128[j], C[j], W);

            float4 ov;
            ov.x = th + d[j][0];  th = fmaf(a[j], th, b[j][0]);
            ov.y = th + d[j][1];  th = fmaf(a[j], th, b[j][1]);
            ov.z = th + d[j][2];  th = fmaf(a[j], th, b[j][2]);
            ov.w = th + d[j][3];
            *(float4*)(outp + (size_t)j * T_DIM + tb) = ov;
        }
    }
}

extern "C" void kernel_launch(void* const* d_in, const int* in_sizes, int n_in,
                              void* d_out, int out_size) {
    const float* X     = (const float*)d_in[0];
    const float* Z     = (const float*)d_in[1];
    const float* G     = (const float*)d_in[2];
    const float* eta   = (const float*)d_in[3];
    const float* zeta  = (const float*)d_in[4];
    const float* gamma = (const float*)d_in[5];
    float* out = (float*)d_out;

    cudaFuncSetAttribute(dlm_kernel,
                         cudaFuncAttributeMaxDynamicSharedMemorySize, SMEM_BYTES);
    dlm_kernel<<<GRID, NT, SMEM_BYTES>>>(X, Z, G, eta, zeta, gamma, out);
}